// round 2
// baseline (speedup 1.0000x reference)
#include <cuda_runtime.h>

// ---------------------------------------------------------------------------
// GCN_dgl: 2-layer symmetric-normalized GCN + max-pool readout + linear head
//   Inputs (metadata order): x[50000,96] f32, src[800000] i32, dst[800000] i32,
//                            W1[96,96], b1[96], W2[96,96], b2[96], Wl[96,2], bl[2]
//   Output: [1,2] f32
// ---------------------------------------------------------------------------

constexpr int NN = 50000;
constexpr int NE = 800000;
constexpr int D  = 96;

// Scratch (allocation-free: __device__ globals)
__device__ float        g_deg_out[NN];
__device__ float        g_deg_in[NN];
__device__ float        g_norm_src[NN];
__device__ float        g_norm_dst[NN];
__device__ float        g_agg[(size_t)NN * D];   // SpMM accumulator (reused per layer)
__device__ float        g_h1[(size_t)NN * D];    // layer-1 activations
__device__ unsigned int g_max[D];                // max-pool accumulator (uint-ordered floats >= 0)

// --- degree histogram ------------------------------------------------------
__global__ void deg_kernel(const int* __restrict__ src, const int* __restrict__ dst) {
    int i = blockIdx.x * blockDim.x + threadIdx.x;
    if (i < NE) {
        atomicAdd(&g_deg_out[src[i]], 1.0f);
        atomicAdd(&g_deg_in [dst[i]], 1.0f);
    }
}

// --- norms: deg^{-1/2}, zero-degree clamped to 1 ---------------------------
__global__ void norm_kernel() {
    int i = blockIdx.x * blockDim.x + threadIdx.x;
    if (i < NN) {
        float dO = g_deg_out[i];
        float dI = g_deg_in[i];
        g_norm_src[i] = (dO > 0.f) ? rsqrtf(dO) : 1.0f;
        g_norm_dst[i] = (dI > 0.f) ? rsqrtf(dI) : 1.0f;
    }
}

// --- SpMM scatter: agg[dst] += in[src] * norm_src[src], one warp per edge --
__global__ void scatter_kernel(const float* __restrict__ in,
                               const int*   __restrict__ src,
                               const int*   __restrict__ dst) {
    int gtid = blockIdx.x * blockDim.x + threadIdx.x;
    int e    = gtid >> 5;
    int lane = gtid & 31;
    if (e >= NE) return;
    int   s  = src[e];
    int   d  = dst[e];
    float ns = g_norm_src[s];
    const float* xr = in    + (size_t)s * D;
    float*       ar = g_agg + (size_t)d * D;
    #pragma unroll
    for (int f = lane; f < D; f += 32)
        atomicAdd(&ar[f], xr[f] * ns);
}

// --- dense layer: out = act( (agg * norm_dst) @ W + b ) --------------------
// (agg*norm_dst)@W == norm_dst*(agg@W) row-wise, so the norm folds into the
// epilogue. MODE 0: write relu(h) to out. MODE 1: fold relu(h) into g_max.
// Block: (96, 2); each thread owns output feature j for 8 nodes.
template <int MODE>
__global__ void __launch_bounds__(192)
dense_kernel(const float* __restrict__ in, const float* __restrict__ W,
             const float* __restrict__ b,  float* __restrict__ out) {
    __shared__ float Ws[D * D];       // 36864 B
    __shared__ float Rs[2][8][D];     //  6144 B

    int j = threadIdx.x;              // 0..95 : output feature
    int y = threadIdx.y;              // 0..1  : node sub-group
    int t = y * 96 + j;

    for (int idx = t; idx < D * D; idx += 192) Ws[idx] = W[idx];

    int n0 = blockIdx.x * 16 + y * 8;
    #pragma unroll
    for (int m = 0; m < 8; m++) {
        int n = n0 + m;
        Rs[y][m][j] = (n < NN) ? in[(size_t)n * D + j] : 0.f;
    }
    __syncthreads();

    float acc[8];
    #pragma unroll
    for (int m = 0; m < 8; m++) acc[m] = 0.f;

    #pragma unroll 8
    for (int k = 0; k < D; k++) {
        float w = Ws[k * D + j];
        #pragma unroll
        for (int m = 0; m < 8; m++) acc[m] += Rs[y][m][k] * w;
    }

    float bj = b[j];
    if (MODE == 0) {
        #pragma unroll
        for (int m = 0; m < 8; m++) {
            int n = n0 + m;
            if (n < NN) {
                float v = fmaf(acc[m], g_norm_dst[n], bj);
                out[(size_t)n * D + j] = fmaxf(v, 0.f);
            }
        }
    } else {
        float mx = 0.f;   // relu output >= 0, so 0 is identity for the max
        #pragma unroll
        for (int m = 0; m < 8; m++) {
            int n = n0 + m;
            if (n < NN) {
                float v = fmaxf(fmaf(acc[m], g_norm_dst[n], bj), 0.f);
                mx = fmaxf(mx, v);
            }
        }
        // non-negative floats: uint ordering == float ordering
        atomicMax(&g_max[j], __float_as_uint(mx));
    }
}

// --- head: out[1,2] = gmax @ Wl + bl ----------------------------------------
__global__ void final_kernel(const float* __restrict__ Wl,
                             const float* __restrict__ bl,
                             float* __restrict__ out) {
    int c = threadIdx.x;
    if (c < 2) {
        float acc = bl[c];
        #pragma unroll 8
        for (int k = 0; k < D; k++)
            acc += __uint_as_float(g_max[k]) * Wl[k * 2 + c];
        out[c] = acc;
    }
}

extern "C" void kernel_launch(void* const* d_in, const int* in_sizes, int n_in,
                              void* d_out, int out_size) {
    const float* x   = (const float*)d_in[0];
    const int*   src = (const int*)  d_in[1];
    const int*   dst = (const int*)  d_in[2];
    const float* W1  = (const float*)d_in[3];
    const float* b1  = (const float*)d_in[4];
    const float* W2  = (const float*)d_in[5];
    const float* b2  = (const float*)d_in[6];
    const float* Wl  = (const float*)d_in[7];
    const float* bl  = (const float*)d_in[8];
    float* out = (float*)d_out;

    // Host-visible device addresses of the __device__ scratch (NOTE: the
    // symbol name itself is NOT a valid device pointer in host code!)
    void *pdo, *pdi, *pagg, *ph1, *pmax;
    cudaGetSymbolAddress(&pdo,  g_deg_out);
    cudaGetSymbolAddress(&pdi,  g_deg_in);
    cudaGetSymbolAddress(&pagg, g_agg);
    cudaGetSymbolAddress(&ph1,  g_h1);
    cudaGetSymbolAddress(&pmax, g_max);
    float* agg = (float*)pagg;
    float* h1  = (float*)ph1;

    // Re-zero all accumulator state each call (graph replays must be deterministic)
    cudaMemsetAsync(pdo,  0, NN * sizeof(float));
    cudaMemsetAsync(pdi,  0, NN * sizeof(float));
    cudaMemsetAsync(pagg, 0, (size_t)NN * D * sizeof(float));
    cudaMemsetAsync(pmax, 0, D * sizeof(unsigned int));

    deg_kernel <<<(NE + 255) / 256, 256>>>(src, dst);
    norm_kernel<<<(NN + 255) / 256, 256>>>();

    // Layer 1: scatter x*norm_src -> agg, then h1 = relu((agg@W1)*norm_dst + b1)
    {
        int blocks = (NE + 7) / 8;            // one warp per edge, 8 warps/block
        scatter_kernel<<<blocks, 256>>>(x, src, dst);
    }
    dense_kernel<0><<<(NN + 15) / 16, dim3(96, 2)>>>(agg, W1, b1, h1);

    // Layer 2: re-zero agg, scatter h1*norm_src, fused dense + max-pool
    cudaMemsetAsync(pagg, 0, (size_t)NN * D * sizeof(float));
    {
        int blocks = (NE + 7) / 8;
        scatter_kernel<<<blocks, 256>>>(h1, src, dst);
    }
    dense_kernel<1><<<(NN + 15) / 16, dim3(96, 2)>>>(agg, W2, b2, nullptr);

    final_kernel<<<1, 32>>>(Wl, bl, out);
}

// round 3
// speedup vs baseline: 1.0049x; 1.0049x over previous
#include <cuda_runtime.h>

// ---------------------------------------------------------------------------
// GCN_dgl: 2-layer symmetric-normalized GCN + max-pool readout + linear head
//   Inputs (metadata order): x[50000,96] f32, src[800000] i32, dst[800000] i32,
//                            W1[96,96], b1[96], W2[96,96], b2[96], Wl[96,2], bl[2]
//   Output: [1,2] f32
// ---------------------------------------------------------------------------

constexpr int NN = 50000;
constexpr int NE = 800000;
constexpr int D  = 96;

// Scratch (allocation-free: __device__ globals)
__device__ float        g_deg_out[NN];
__device__ float        g_deg_in[NN];
__device__ float        g_norm_src[NN];
__device__ float        g_norm_dst[NN];
__device__ float        g_agg[(size_t)NN * D];   // SpMM accumulator (reused per layer)
__device__ float        g_h1[(size_t)NN * D];    // layer-1 activations
__device__ unsigned int g_max[D];                // max-pool accumulator (uint-ordered floats >= 0)

// --- degree histogram ------------------------------------------------------
__global__ void deg_kernel(const int* __restrict__ src, const int* __restrict__ dst) {
    int i = blockIdx.x * blockDim.x + threadIdx.x;
    if (i < NE) {
        atomicAdd(&g_deg_out[src[i]], 1.0f);
        atomicAdd(&g_deg_in [dst[i]], 1.0f);
    }
}

// --- norms: deg^{-1/2}, zero-degree clamped to 1 ---------------------------
__global__ void norm_kernel() {
    int i = blockIdx.x * blockDim.x + threadIdx.x;
    if (i < NN) {
        float dO = g_deg_out[i];
        float dI = g_deg_in[i];
        g_norm_src[i] = (dO > 0.f) ? rsqrtf(dO) : 1.0f;
        g_norm_dst[i] = (dI > 0.f) ? rsqrtf(dI) : 1.0f;
    }
}

// --- SpMM scatter: agg[dst] += in[src] * norm_src[src], one warp per edge --
__global__ void scatter_kernel(const float* __restrict__ in,
                               const int*   __restrict__ src,
                               const int*   __restrict__ dst) {
    int gtid = blockIdx.x * blockDim.x + threadIdx.x;
    int e    = gtid >> 5;
    int lane = gtid & 31;
    if (e >= NE) return;
    int   s  = src[e];
    int   d  = dst[e];
    float ns = g_norm_src[s];
    const float* xr = in    + (size_t)s * D;
    float*       ar = g_agg + (size_t)d * D;
    #pragma unroll
    for (int f = lane; f < D; f += 32)
        atomicAdd(&ar[f], xr[f] * ns);
}

// --- dense layer: out = act( (agg * norm_dst) @ W + b ) --------------------
// (agg*norm_dst)@W == norm_dst*(agg@W) row-wise, so the norm folds into the
// epilogue. MODE 0: write relu(h) to out. MODE 1: fold relu(h) into g_max.
// Block: (96, 2); each thread owns output feature j for 8 nodes.
template <int MODE>
__global__ void __launch_bounds__(192)
dense_kernel(const float* __restrict__ in, const float* __restrict__ W,
             const float* __restrict__ b,  float* __restrict__ out) {
    __shared__ float Ws[D * D];       // 36864 B
    __shared__ float Rs[2][8][D];     //  6144 B

    int j = threadIdx.x;              // 0..95 : output feature
    int y = threadIdx.y;              // 0..1  : node sub-group
    int t = y * 96 + j;

    for (int idx = t; idx < D * D; idx += 192) Ws[idx] = W[idx];

    int n0 = blockIdx.x * 16 + y * 8;
    #pragma unroll
    for (int m = 0; m < 8; m++) {
        int n = n0 + m;
        Rs[y][m][j] = (n < NN) ? in[(size_t)n * D + j] : 0.f;
    }
    __syncthreads();

    float acc[8];
    #pragma unroll
    for (int m = 0; m < 8; m++) acc[m] = 0.f;

    #pragma unroll 8
    for (int k = 0; k < D; k++) {
        float w = Ws[k * D + j];
        #pragma unroll
        for (int m = 0; m < 8; m++) acc[m] += Rs[y][m][k] * w;
    }

    float bj = b[j];
    if (MODE == 0) {
        #pragma unroll
        for (int m = 0; m < 8; m++) {
            int n = n0 + m;
            if (n < NN) {
                float v = fmaf(acc[m], g_norm_dst[n], bj);
                out[(size_t)n * D + j] = fmaxf(v, 0.f);
            }
        }
    } else {
        float mx = 0.f;   // relu output >= 0, so 0 is identity for the max
        #pragma unroll
        for (int m = 0; m < 8; m++) {
            int n = n0 + m;
            if (n < NN) {
                float v = fmaxf(fmaf(acc[m], g_norm_dst[n], bj), 0.f);
                mx = fmaxf(mx, v);
            }
        }
        // non-negative floats: uint ordering == float ordering
        atomicMax(&g_max[j], __float_as_uint(mx));
    }
}

// --- head: out[1,2] = gmax @ Wl + bl ----------------------------------------
__global__ void final_kernel(const float* __restrict__ Wl,
                             const float* __restrict__ bl,
                             float* __restrict__ out) {
    int c = threadIdx.x;
    if (c < 2) {
        float acc = bl[c];
        #pragma unroll 8
        for (int k = 0; k < D; k++)
            acc += __uint_as_float(g_max[k]) * Wl[k * 2 + c];
        out[c] = acc;
    }
}

extern "C" void kernel_launch(void* const* d_in, const int* in_sizes, int n_in,
                              void* d_out, int out_size) {
    const float* x   = (const float*)d_in[0];
    const int*   src = (const int*)  d_in[1];
    const int*   dst = (const int*)  d_in[2];
    const float* W1  = (const float*)d_in[3];
    const float* b1  = (const float*)d_in[4];
    const float* W2  = (const float*)d_in[5];
    const float* b2  = (const float*)d_in[6];
    const float* Wl  = (const float*)d_in[7];
    const float* bl  = (const float*)d_in[8];
    float* out = (float*)d_out;

    // Host-visible device addresses of the __device__ scratch (NOTE: the
    // symbol name itself is NOT a valid device pointer in host code!)
    void *pdo, *pdi, *pagg, *ph1, *pmax;
    cudaGetSymbolAddress(&pdo,  g_deg_out);
    cudaGetSymbolAddress(&pdi,  g_deg_in);
    cudaGetSymbolAddress(&pagg, g_agg);
    cudaGetSymbolAddress(&ph1,  g_h1);
    cudaGetSymbolAddress(&pmax, g_max);
    float* agg = (float*)pagg;
    float* h1  = (float*)ph1;

    // Re-zero all accumulator state each call (graph replays must be deterministic)
    cudaMemsetAsync(pdo,  0, NN * sizeof(float));
    cudaMemsetAsync(pdi,  0, NN * sizeof(float));
    cudaMemsetAsync(pagg, 0, (size_t)NN * D * sizeof(float));
    cudaMemsetAsync(pmax, 0, D * sizeof(unsigned int));

    deg_kernel <<<(NE + 255) / 256, 256>>>(src, dst);
    norm_kernel<<<(NN + 255) / 256, 256>>>();

    // Layer 1: scatter x*norm_src -> agg, then h1 = relu((agg@W1)*norm_dst + b1)
    {
        int blocks = (NE + 7) / 8;            // one warp per edge, 8 warps/block
        scatter_kernel<<<blocks, 256>>>(x, src, dst);
    }
    dense_kernel<0><<<(NN + 15) / 16, dim3(96, 2)>>>(agg, W1, b1, h1);

    // Layer 2: re-zero agg, scatter h1*norm_src, fused dense + max-pool
    cudaMemsetAsync(pagg, 0, (size_t)NN * D * sizeof(float));
    {
        int blocks = (NE + 7) / 8;
        scatter_kernel<<<blocks, 256>>>(h1, src, dst);
    }
    dense_kernel<1><<<(NN + 15) / 16, dim3(96, 2)>>>(agg, W2, b2, nullptr);

    final_kernel<<<1, 32>>>(Wl, bl, out);
}

// round 4
// speedup vs baseline: 1.4019x; 1.3950x over previous
#include <cuda_runtime.h>

// ---------------------------------------------------------------------------
// GCN_dgl: 2-layer symmetric-normalized GCN + max-pool readout + linear head
//   x[50000,96] f32, src/dst[800000] i32, W1/W2[96,96], b1/b2[96], Wl[96,2], bl[2]
//   Output: [1,2] f32
// Strategy: in-graph CSR build (dst-grouped), pull-gather SpMM (no feature
// atomics, no agg memset), float4-staged dense GEMM, fused norms + maxpool.
// ---------------------------------------------------------------------------

constexpr int NN = 50000;
constexpr int NE = 800000;
constexpr int D  = 96;
constexpr int SCAN_NB = (NN + 255) / 256;   // 196 scan blocks

// Scratch (allocation-free: __device__ globals)
__device__ int          g_degi_out[NN];
__device__ int          g_degi_in[NN];
__device__ float        g_norm_src[NN];
__device__ float        g_norm_dst[NN];
__device__ int          g_offs[NN + 1];     // CSR row offsets (by dst)
__device__ int          g_blocksums[256];   // scan spine
__device__ int          g_fill[NN];         // bucket fill counters
__device__ int          g_csr[NE];          // src index per CSR slot
__device__ float        g_agg[(size_t)NN * D];
__device__ float        g_h1[(size_t)NN * D];
__device__ unsigned int g_max[D];           // uint-ordered non-negative floats

// --- degree histogram (int atomics) ----------------------------------------
__global__ void deg_kernel(const int* __restrict__ src, const int* __restrict__ dst) {
    int i = blockIdx.x * blockDim.x + threadIdx.x;
    if (i < NE) {
        atomicAdd(&g_degi_out[src[i]], 1);
        atomicAdd(&g_degi_in [dst[i]], 1);
    }
}

// --- norms ------------------------------------------------------------------
__global__ void norm_kernel() {
    int i = blockIdx.x * blockDim.x + threadIdx.x;
    if (i < NN) {
        int dO = g_degi_out[i];
        int dI = g_degi_in[i];
        g_norm_src[i] = (dO > 0) ? rsqrtf((float)dO) : 1.0f;
        g_norm_dst[i] = (dI > 0) ? rsqrtf((float)dI) : 1.0f;
    }
}

// --- 3-kernel exclusive scan of g_degi_in -> g_offs -------------------------
__global__ void scan1_kernel() {
    __shared__ int sh[256];
    int t = threadIdx.x;
    int i = blockIdx.x * 256 + t;
    int v = (i < NN) ? g_degi_in[i] : 0;
    sh[t] = v;
    __syncthreads();
    #pragma unroll
    for (int off = 1; off < 256; off <<= 1) {
        int a = (t >= off) ? sh[t - off] : 0;
        __syncthreads();
        sh[t] += a;
        __syncthreads();
    }
    if (i < NN) g_offs[i] = sh[t] - v;           // exclusive within block
    if (t == 255) g_blocksums[blockIdx.x] = sh[255];
}

__global__ void scan2_kernel() {                  // single block of 256
    __shared__ int sh[256];
    int t = threadIdx.x;
    int v = (t < SCAN_NB) ? g_blocksums[t] : 0;
    sh[t] = v;
    __syncthreads();
    #pragma unroll
    for (int off = 1; off < 256; off <<= 1) {
        int a = (t >= off) ? sh[t - off] : 0;
        __syncthreads();
        sh[t] += a;
        __syncthreads();
    }
    g_blocksums[t] = sh[t] - v;                   // exclusive spine
}

__global__ void scan3_kernel() {
    int i = blockIdx.x * 256 + threadIdx.x;
    if (i < NN) g_offs[i] += g_blocksums[blockIdx.x];
    if (i == 0) g_offs[NN] = NE;
}

// --- CSR bucket fill ---------------------------------------------------------
__global__ void fill_kernel(const int* __restrict__ src, const int* __restrict__ dst) {
    int e = blockIdx.x * blockDim.x + threadIdx.x;
    if (e < NE) {
        int d   = dst[e];
        int pos = g_offs[d] + atomicAdd(&g_fill[d], 1);
        g_csr[pos] = src[e];
    }
}

// --- pull-gather SpMM: agg[n] = sum_{s in N(n)} in[s] * (SCALE ? norm_src[s] : 1)
// One warp per dst node; each lane owns features {lane, lane+32, lane+64}.
template <bool SCALE>
__global__ void __launch_bounds__(256)
gather_kernel(const float* __restrict__ in, float* __restrict__ agg) {
    int gtid = blockIdx.x * blockDim.x + threadIdx.x;
    int n    = gtid >> 5;
    int lane = gtid & 31;
    if (n >= NN) return;
    int p  = g_offs[n];
    int p1 = g_offs[n + 1];
    float a0 = 0.f, a1 = 0.f, a2 = 0.f;

    for (; p + 4 <= p1; p += 4) {                 // unroll 4 for MLP
        int s0 = g_csr[p], s1 = g_csr[p + 1], s2 = g_csr[p + 2], s3 = g_csr[p + 3];
        const float* r0 = in + (size_t)s0 * D;
        const float* r1 = in + (size_t)s1 * D;
        const float* r2 = in + (size_t)s2 * D;
        const float* r3 = in + (size_t)s3 * D;
        float n0 = SCALE ? g_norm_src[s0] : 1.f;
        float n1 = SCALE ? g_norm_src[s1] : 1.f;
        float n2 = SCALE ? g_norm_src[s2] : 1.f;
        float n3 = SCALE ? g_norm_src[s3] : 1.f;
        a0 += r0[lane]      * n0 + r1[lane]      * n1 + r2[lane]      * n2 + r3[lane]      * n3;
        a1 += r0[lane + 32] * n0 + r1[lane + 32] * n1 + r2[lane + 32] * n2 + r3[lane + 32] * n3;
        a2 += r0[lane + 64] * n0 + r1[lane + 64] * n1 + r2[lane + 64] * n2 + r3[lane + 64] * n3;
    }
    for (; p < p1; ++p) {
        int s = g_csr[p];
        const float* r = in + (size_t)s * D;
        float ns = SCALE ? g_norm_src[s] : 1.f;
        a0 += r[lane] * ns; a1 += r[lane + 32] * ns; a2 += r[lane + 64] * ns;
    }
    float* ar = agg + (size_t)n * D;
    ar[lane] = a0; ar[lane + 32] = a1; ar[lane + 64] = a2;
}

// --- dense layer: h = relu( (agg @ W) * norm_dst + b ) ----------------------
// MODE 0: out[n][j] = relu(...) * norm_src[n]   (pre-scaled for next gather)
// MODE 1: fold relu(...) into per-feature max (uint atomicMax, values >= 0)
// Block (96,2): thread owns feature j for 8 nodes. Inner loop per 4 k's:
// 8 float4 broadcast LDS (node rows) + 4 conflict-free scalar LDS (W) / 32 FMA.
template <int MODE>
__global__ void __launch_bounds__(192)
dense_kernel(const float* __restrict__ in, const float* __restrict__ W,
             const float* __restrict__ b,  float* __restrict__ out) {
    __shared__ float  Ws[D * D];                 // 36864 B, [k][j]
    __shared__ float4 Rs4[2][8][D / 4];          //  6144 B, node rows as float4

    int j = threadIdx.x;              // 0..95 output feature
    int y = threadIdx.y;              // 0..1  node sub-group
    int t = y * 96 + j;

    for (int idx = t; idx < D * D; idx += 192) Ws[idx] = W[idx];

    int n0 = blockIdx.x * 16 + y * 8;
    #pragma unroll
    for (int m = 0; m < 8; m++) {
        int n = n0 + m;
        ((float*)&Rs4[y][m][0])[j] = (n < NN) ? in[(size_t)n * D + j] : 0.f;
    }
    __syncthreads();

    float acc[8];
    #pragma unroll
    for (int m = 0; m < 8; m++) acc[m] = 0.f;

    #pragma unroll 6
    for (int k4 = 0; k4 < D / 4; k4++) {
        float w0 = Ws[(4 * k4 + 0) * D + j];
        float w1 = Ws[(4 * k4 + 1) * D + j];
        float w2 = Ws[(4 * k4 + 2) * D + j];
        float w3 = Ws[(4 * k4 + 3) * D + j];
        #pragma unroll
        for (int m = 0; m < 8; m++) {
            float4 r = Rs4[y][m][k4];
            acc[m] = fmaf(r.x, w0, acc[m]);
            acc[m] = fmaf(r.y, w1, acc[m]);
            acc[m] = fmaf(r.z, w2, acc[m]);
            acc[m] = fmaf(r.w, w3, acc[m]);
        }
    }

    float bj = b[j];
    if (MODE == 0) {
        #pragma unroll
        for (int m = 0; m < 8; m++) {
            int n = n0 + m;
            if (n < NN) {
                float v = fmaxf(fmaf(acc[m], g_norm_dst[n], bj), 0.f);
                out[(size_t)n * D + j] = v * g_norm_src[n];   // pre-scale for layer-2 gather
            }
        }
    } else {
        float mx = 0.f;
        #pragma unroll
        for (int m = 0; m < 8; m++) {
            int n = n0 + m;
            if (n < NN) {
                float v = fmaxf(fmaf(acc[m], g_norm_dst[n], bj), 0.f);
                mx = fmaxf(mx, v);
            }
        }
        atomicMax(&g_max[j], __float_as_uint(mx));
    }
}

// --- head: out[1,2] = gmax @ Wl + bl ----------------------------------------
__global__ void final_kernel(const float* __restrict__ Wl,
                             const float* __restrict__ bl,
                             float* __restrict__ out) {
    int c = threadIdx.x;
    if (c < 2) {
        float acc = bl[c];
        #pragma unroll 8
        for (int k = 0; k < D; k++)
            acc += __uint_as_float(g_max[k]) * Wl[k * 2 + c];
        out[c] = acc;
    }
}

extern "C" void kernel_launch(void* const* d_in, const int* in_sizes, int n_in,
                              void* d_out, int out_size) {
    const float* x   = (const float*)d_in[0];
    const int*   src = (const int*)  d_in[1];
    const int*   dst = (const int*)  d_in[2];
    const float* W1  = (const float*)d_in[3];
    const float* b1  = (const float*)d_in[4];
    const float* W2  = (const float*)d_in[5];
    const float* b2  = (const float*)d_in[6];
    const float* Wl  = (const float*)d_in[7];
    const float* bl  = (const float*)d_in[8];
    float* out = (float*)d_out;

    // Host-visible device addresses (symbol names are NOT device ptrs on host)
    void *pdo, *pdi, *pfill, *pmax, *pagg, *ph1;
    cudaGetSymbolAddress(&pdo,   g_degi_out);
    cudaGetSymbolAddress(&pdi,   g_degi_in);
    cudaGetSymbolAddress(&pfill, g_fill);
    cudaGetSymbolAddress(&pmax,  g_max);
    cudaGetSymbolAddress(&pagg,  g_agg);
    cudaGetSymbolAddress(&ph1,   g_h1);
    float* agg = (float*)pagg;
    float* h1  = (float*)ph1;

    // Re-zero per-call accumulator state (cheap: 600 KB total)
    cudaMemsetAsync(pdo,   0, NN * sizeof(int));
    cudaMemsetAsync(pdi,   0, NN * sizeof(int));
    cudaMemsetAsync(pfill, 0, NN * sizeof(int));
    cudaMemsetAsync(pmax,  0, D * sizeof(unsigned int));

    // Graph structure: degrees, norms, CSR (dst-grouped)
    deg_kernel <<<(NE + 255) / 256, 256>>>(src, dst);
    norm_kernel<<<(NN + 255) / 256, 256>>>();
    scan1_kernel<<<SCAN_NB, 256>>>();
    scan2_kernel<<<1, 256>>>();
    scan3_kernel<<<SCAN_NB, 256>>>();
    fill_kernel<<<(NE + 255) / 256, 256>>>(src, dst);

    int gblocks = (NN * 32 + 255) / 256;   // one warp per node

    // Layer 1: agg = A_hat-gather(x * norm_src);  h1 = relu((agg@W1)*nd + b1)*ns
    gather_kernel<true ><<<gblocks, 256>>>(x, agg);
    dense_kernel <0    ><<<(NN + 15) / 16, dim3(96, 2)>>>(agg, W1, b1, h1);

    // Layer 2: agg = gather(h1)  (h1 already src-scaled); dense + fused maxpool
    gather_kernel<false><<<gblocks, 256>>>(h1, agg);
    dense_kernel <1    ><<<(NN + 15) / 16, dim3(96, 2)>>>(agg, W2, b2, nullptr);

    final_kernel<<<1, 32>>>(Wl, bl, out);
}